// round 12
// baseline (speedup 1.0000x reference)
#include <cuda_runtime.h>
#include <cuda_bf16.h>
#include <cuda_fp16.h>

typedef unsigned int u32;
typedef unsigned char u8;
typedef unsigned short u16;

#define ROWS 65536
#define NBSTRIDE 33792
#define MIDB 1088              // padded e4m3 concat stride (1056 data + 32 zeros)
#define HFW 800                // f16 mirror width: x(32)+h1+h2+h3 (3*256)
#define MIN_VAL (-10000000.0f)
#define GRID_P 304

// ---------------- persistent scratch (BSS, zero-init) ----------------
__device__ u8    g_hc [(size_t)ROWS * MIDB];   // fp8: [x | h1..h4 | zeros]
__device__ u16   g_hf [(size_t)ROWS * HFW];    // f16 mirror: [x | h1 | h2 | h3]
__device__ u8    g_w0t[256 * 64];              // W0^T [N=256][K=64], k>=32 zero
__device__ u8    g_wst[3][256 * 256];          // Ws^T fp8
__device__ u8    g_w1t[(size_t)512 * 1088];    // W1^T fp8, k>=1056 zero
__device__ float g_part[2 * ROWS];
__device__ float g_sc[512], g_sh[512];
__device__ u32   g_ctr[8];

// ---------------- helpers ----------------
__device__ __forceinline__ u32 s2u(const void* p){
    u32 a;
    asm("{ .reg .u64 t; cvta.to.shared.u64 t, %1; cvt.u32.u64 %0, t; }" : "=r"(a) : "l"(p));
    return a;
}
__device__ __forceinline__ void cpa16(u32 dst, const void* src){
    asm volatile("cp.async.cg.shared.global [%0], [%1], 16;" :: "r"(dst), "l"(src));
}
#define CP_COMMIT() asm volatile("cp.async.commit_group;" ::: "memory")
#define CP_WAIT(n)  asm volatile("cp.async.wait_group %0;" :: "n"(n) : "memory")

__device__ __forceinline__ void mma_fp8_h(u32* c, const u32* a, const u32* b){
    asm volatile("mma.sync.aligned.m16n8k32.row.col.f16.e4m3.e4m3.f16 "
        "{%0,%1}, {%2,%3,%4,%5}, {%6,%7}, {%0,%1};"
        : "+r"(c[0]), "+r"(c[1])
        : "r"(a[0]), "r"(a[1]), "r"(a[2]), "r"(a[3]), "r"(b[0]), "r"(b[1]));
}
#define LDSM4(r0, r1, r2, r3, addr) \
    asm volatile("ldmatrix.sync.aligned.m8n8.x4.shared.b16 {%0,%1,%2,%3}, [%4];" \
        : "=r"(r0), "=r"(r1), "=r"(r2), "=r"(r3) : "r"(addr))

__device__ __forceinline__ u16 pk8(float lo, float hi){
    u16 t;
    asm("cvt.rn.satfinite.e4m3x2.f32 %0, %1, %2;" : "=h"(t) : "f"(hi), "f"(lo));
    return t;
}
__device__ __forceinline__ u8 cvt1(float v){ return (u8)(pk8(v, 0.f) & 0xff); }
__device__ __forceinline__ float2 h2f(u32 h){
    return __half22float2(*reinterpret_cast<__half2*>(&h));
}
__device__ __forceinline__ void hadd2(u32& a, u32 b){
    asm("add.rn.f16x2 %0, %0, %1;" : "+r"(a) : "r"(b));
}
__device__ __forceinline__ u32 pack2h(u32 h0, u32 h1){   // 2x f16x2 -> 4x e4m3
    u16 a, b;
    asm("cvt.rn.satfinite.e4m3x2.f16x2 %0, %1;" : "=h"(a) : "r"(h0));
    asm("cvt.rn.satfinite.e4m3x2.f16x2 %0, %1;" : "=h"(b) : "r"(h1));
    return (u32)a | ((u32)b << 16);
}
__device__ __forceinline__ u32 f2h2(float a, float b){
    __half2 h = __floats2half2_rn(a, b);
    return *reinterpret_cast<u32*>(&h);
}

// ---------------- merged prep kernel ----------------
__global__ void prep_all(const float* __restrict__ W0, const float* __restrict__ Ws,
                         const float* __restrict__ W1,
                         const float* __restrict__ bn_g, const float* __restrict__ bn_b,
                         const float* __restrict__ bn_m, const float* __restrict__ bn_v){
    int blk = blockIdx.x, tid = threadIdx.x;
    if (blk < 32){
        int i = blk * 256 + tid;
        int n = i >> 5, k = i & 31;
        g_w0t[n * 64 + k] = cvt1(W0[k * 256 + n]);
    } else if (blk < 800){
        int i = (blk - 32) * 256 + tid;
        int l = i >> 16, r = i & 65535;
        int n = r >> 8, k = r & 255;
        g_wst[l][n * 256 + k] = cvt1(Ws[l * 65536 + k * 256 + n]);
    } else if (blk < 2976){
        int i = (blk - 800) * 256 + tid;
        int n = i / 1088, k = i - n * 1088;
        g_w1t[i] = (k < 1056) ? cvt1(W1[k * 512 + n]) : (u8)0;
    } else {
        int i = (blk - 2976) * 256 + tid;
        if (i < 512){
            float sc = bn_g[i] * rsqrtf(bn_v[i] + 1e-5f);
            g_sc[i] = sc;
            g_sh[i] = bn_b[i] - bn_m[i] * sc;
        }
    }
}

__global__ void xcvt(const float* __restrict__ obs){
    int q = blockIdx.x * 256 + threadIdx.x;
    int row = q >> 2, j = q & 3;
    int b = row >> 10, n = row & 1023;
    const float4* s = reinterpret_cast<const float4*>(obs + (size_t)b * NBSTRIDE + 1024 + n * 32 + j * 8);
    float4 a = s[0], c = s[1];
    u32 w0 = (u32)pk8(a.x, a.y) | ((u32)pk8(a.z, a.w) << 16);
    u32 w1 = (u32)pk8(c.x, c.y) | ((u32)pk8(c.z, c.w) << 16);
    *reinterpret_cast<uint2*>(g_hc + (size_t)row * MIDB + j * 8) = make_uint2(w0, w1);
    *reinterpret_cast<uint4*>(g_hf + (size_t)row * HFW + j * 8) =
        make_uint4(f2h2(a.x, a.y), f2h2(a.z, a.w), f2h2(c.x, c.y), f2h2(c.z, c.w));
}

// ---------------- persistent FP8 GEMM, f16-source fused agg ----------------
// Tile 64x256, 256 thr, occ 2, 8 warps, warp tile 32x64. K chunk = 64 (2 k32 mma).
// 3-stage. Stage: A 64x80 @0 (5120), B 256x80 @5120 (20480) = 25600.
// red @76800, musd @78848. Total 79360.
#define SMTOT 79360
template<int KFULL, bool LN, bool AGG, int AW, bool MIRROR>
__global__ void __launch_bounds__(256, 2)
gemm_mma(const u8* __restrict__ A, const u16* __restrict__ Af,
         const u8* __restrict__ Bt, int slot, int ntiles,
         const float* __restrict__ bias, const float* __restrict__ gamma,
         const float* __restrict__ beta, u8* __restrict__ outp, u16* __restrict__ outf)
{
    extern __shared__ char sm[];
    __shared__ u32 s_tile;
    const u32 sb = s2u(sm);
    const int tid  = threadIdx.x;
    const int lane = tid & 31, wid = tid >> 5;
    const int wm = wid & 1, wn = wid >> 1;
    constexpr int NC = KFULL / 64;

    const int ar = tid >> 2, aseg = tid & 3;        // A loader: 64 rows x 4 x 16B segs

    for (;;){
        __syncthreads();
        if (tid == 0) s_tile = atomicAdd(&g_ctr[slot], 1u);
        __syncthreads();
        const u32 t = s_tile;
        if (t >= (u32)ntiles) break;

        const int row0  = LN ? ((int)t << 6) : ((int)(t >> 1) << 6);
        const int ncol0 = LN ? 0 : ((int)(t & 1) << 8);
        const u8* Bp = Bt + (size_t)ncol0 * KFULL;

        const int arow = row0 + ar;
        const int an = arow & 1023, agr = an >> 5, agc = an & 31;
        const u16* abase = Af + (size_t)arow * HFW;     // f16 agg source row

        // synchronous full agg (prologue only)
        auto aggfull = [&](int kc, int stg){
            const int colb = kc * 64 + aseg * 16;
            uint4 r[8];
#pragma unroll
            for (int e = 0; e < 8; e++) r[e] = make_uint4(0u,0u,0u,0u);
            if (AW == 256 || colb < AW){
                const u16* base = abase + colb;
                if (agc > 0){  r[0] = *(const uint4*)(base - HFW);      r[1] = *(const uint4*)(base - HFW + 8); }
                if (agc < 31){ r[2] = *(const uint4*)(base + HFW);      r[3] = *(const uint4*)(base + HFW + 8); }
                if (agr > 0){  r[4] = *(const uint4*)(base - 32 * HFW); r[5] = *(const uint4*)(base - 32 * HFW + 8); }
                if (agr < 31){ r[6] = *(const uint4*)(base + 32 * HFW); r[7] = *(const uint4*)(base + 32 * HFW + 8); }
            }
            u32 s[8];
#pragma unroll
            for (int e = 0; e < 8; e++) s[e] = 0u;
#pragma unroll
            for (int j = 0; j < 4; j++){
                hadd2(s[0], r[2*j].x); hadd2(s[1], r[2*j].y);
                hadd2(s[2], r[2*j].z); hadd2(s[3], r[2*j].w);
                hadd2(s[4], r[2*j+1].x); hadd2(s[5], r[2*j+1].y);
                hadd2(s[6], r[2*j+1].z); hadd2(s[7], r[2*j+1].w);
            }
            *reinterpret_cast<uint4*>(sm + (u32)stg * 25600u + (u32)(ar * 80 + aseg * 16)) =
                make_uint4(pack2h(s[0], s[1]), pack2h(s[2], s[3]),
                           pack2h(s[4], s[5]), pack2h(s[6], s[7]));
        };
        auto cpA = [&](int kc, int stg){
            cpa16(sb + (u32)stg * 25600u + (u32)(ar * 80 + aseg * 16),
                  A + (size_t)arow * MIDB + kc * 64 + aseg * 16);
        };
        auto cpB = [&](int kc, int stg){
#pragma unroll
            for (int i = 0; i < 4; i++){
                int q = tid + 256 * i;
                int n = q >> 2, seg = q & 3;
                cpa16(sb + (u32)stg * 25600u + 5120u + (u32)(n * 80 + seg * 16),
                      Bp + (size_t)n * KFULL + kc * 64 + seg * 16);
            }
        };

        u32 acc[2][8][2];
#pragma unroll
        for (int mt = 0; mt < 2; mt++)
#pragma unroll
            for (int nt = 0; nt < 8; nt++){ acc[mt][nt][0] = 0u; acc[mt][nt][1] = 0u; }

        // prologue: always 2 committed groups
#pragma unroll
        for (int p = 0; p < 2; p++){
            if (p < NC){
                if (AGG) aggfull(p, p);
                else     cpA(p, p);
                cpB(p, p);
            }
            CP_COMMIT();
        }

        for (int kc = 0; kc < NC; kc++){
            const bool pre = (kc + 2 < NC);
            const int stg2 = (kc + 2) % 3;
            if (pre){
                if (!AGG) cpA(kc + 2, stg2);
                cpB(kc + 2, stg2);
            }
            CP_COMMIT();
            CP_WAIT(2);
            __syncthreads();

            const u32 Ab = sb + (u32)(kc % 3) * 25600u;
            const u32 Bb = Ab + 5120u;

            // split agg prefetch state
            uint4 rn[4];
            u32 sv[8];
            const int colb2 = (kc + 2) * 64 + aseg * 16;
            const bool aggok = AGG && pre && (AW == 256 || colb2 < AW);
            if (AGG && pre){
#pragma unroll
                for (int e = 0; e < 4; e++) rn[e] = make_uint4(0u,0u,0u,0u);
                if (aggok){
                    const u16* base = abase + colb2;
                    if (agc > 0){  rn[0] = *(const uint4*)(base - HFW); rn[1] = *(const uint4*)(base - HFW + 8); }
                    if (agc < 31){ rn[2] = *(const uint4*)(base + HFW); rn[3] = *(const uint4*)(base + HFW + 8); }
                }
            }

            // ks = 0
            {
                u32 a[2][4], b[8][2];
#pragma unroll
                for (int mt = 0; mt < 2; mt++){
                    u32 addr = Ab + (u32)((wm * 32 + mt * 16 + (lane & 7) + ((lane >> 3) & 1) * 8) * 80
                                          + (lane >> 4) * 16);
                    LDSM4(a[mt][0], a[mt][1], a[mt][2], a[mt][3], addr);
                }
#pragma unroll
                for (int np = 0; np < 4; np++){
                    u32 addr = Bb + (u32)((wn * 64 + (np * 2 + (lane >> 4)) * 8 + (lane & 7)) * 80
                                          + ((lane >> 3) & 1) * 16);
                    LDSM4(b[np * 2][0], b[np * 2][1], b[np * 2 + 1][0], b[np * 2 + 1][1], addr);
                }
#pragma unroll
                for (int mt = 0; mt < 2; mt++)
#pragma unroll
                    for (int nt = 0; nt < 8; nt++)
                        mma_fp8_h(acc[mt][nt], a[mt], b[nt]);
            }

            if (AGG && pre){
                // fold L,R; then prefetch U,D
#pragma unroll
                for (int e = 0; e < 8; e++) sv[e] = 0u;
#pragma unroll
                for (int j = 0; j < 2; j++){
                    hadd2(sv[0], rn[2*j].x); hadd2(sv[1], rn[2*j].y);
                    hadd2(sv[2], rn[2*j].z); hadd2(sv[3], rn[2*j].w);
                    hadd2(sv[4], rn[2*j+1].x); hadd2(sv[5], rn[2*j+1].y);
                    hadd2(sv[6], rn[2*j+1].z); hadd2(sv[7], rn[2*j+1].w);
                }
#pragma unroll
                for (int e = 0; e < 4; e++) rn[e] = make_uint4(0u,0u,0u,0u);
                if (aggok){
                    const u16* base = abase + colb2;
                    if (agr > 0){  rn[0] = *(const uint4*)(base - 32 * HFW); rn[1] = *(const uint4*)(base - 32 * HFW + 8); }
                    if (agr < 31){ rn[2] = *(const uint4*)(base + 32 * HFW); rn[3] = *(const uint4*)(base + 32 * HFW + 8); }
                }
            }

            // ks = 1
            {
                u32 a[2][4], b[8][2];
#pragma unroll
                for (int mt = 0; mt < 2; mt++){
                    u32 addr = Ab + (u32)((wm * 32 + mt * 16 + (lane & 7) + ((lane >> 3) & 1) * 8) * 80
                                          + 32 + (lane >> 4) * 16);
                    LDSM4(a[mt][0], a[mt][1], a[mt][2], a[mt][3], addr);
                }
#pragma unroll
                for (int np = 0; np < 4; np++){
                    u32 addr = Bb + (u32)((wn * 64 + (np * 2 + (lane >> 4)) * 8 + (lane & 7)) * 80
                                          + 32 + ((lane >> 3) & 1) * 16);
                    LDSM4(b[np * 2][0], b[np * 2][1], b[np * 2 + 1][0], b[np * 2 + 1][1], addr);
                }
#pragma unroll
                for (int mt = 0; mt < 2; mt++)
#pragma unroll
                    for (int nt = 0; nt < 8; nt++)
                        mma_fp8_h(acc[mt][nt], a[mt], b[nt]);
            }

            if (AGG && pre){
                // fold U,D; pack; STS
#pragma unroll
                for (int j = 0; j < 2; j++){
                    hadd2(sv[0], rn[2*j].x); hadd2(sv[1], rn[2*j].y);
                    hadd2(sv[2], rn[2*j].z); hadd2(sv[3], rn[2*j].w);
                    hadd2(sv[4], rn[2*j+1].x); hadd2(sv[5], rn[2*j+1].y);
                    hadd2(sv[6], rn[2*j+1].z); hadd2(sv[7], rn[2*j+1].w);
                }
                *reinterpret_cast<uint4*>(sm + (u32)stg2 * 25600u + (u32)(ar * 80 + aseg * 16)) =
                    make_uint4(pack2h(sv[0], sv[1]), pack2h(sv[2], sv[3]),
                               pack2h(sv[4], sv[5]), pack2h(sv[6], sv[7]));
            }
        }
        __syncthreads();

        const int cbase = wn * 64 + (lane & 3) * 2;

        if (LN){
            float vf[2][8][4];
            float s1[2][2] = {{0,0},{0,0}}, s2[2][2] = {{0,0},{0,0}};
#pragma unroll
            for (int mt = 0; mt < 2; mt++)
#pragma unroll
                for (int nt = 0; nt < 8; nt++){
                    int c = cbase + nt * 8;
                    float b0 = __ldg(bias + c), b1v = __ldg(bias + c + 1);
                    float2 p0 = h2f(acc[mt][nt][0]);
                    float2 p1 = h2f(acc[mt][nt][1]);
                    float v0 = p0.x + b0, v1 = p0.y + b1v;
                    float v2 = p1.x + b0, v3 = p1.y + b1v;
                    vf[mt][nt][0] = v0; vf[mt][nt][1] = v1;
                    vf[mt][nt][2] = v2; vf[mt][nt][3] = v3;
                    s1[mt][0] += v0 + v1; s2[mt][0] = fmaf(v0, v0, fmaf(v1, v1, s2[mt][0]));
                    s1[mt][1] += v2 + v3; s2[mt][1] = fmaf(v2, v2, fmaf(v3, v3, s2[mt][1]));
                }
#pragma unroll
            for (int o = 1; o <= 2; o <<= 1)
#pragma unroll
                for (int mt = 0; mt < 2; mt++)
#pragma unroll
                    for (int h = 0; h < 2; h++){
                        s1[mt][h] += __shfl_xor_sync(0xffffffffu, s1[mt][h], o);
                        s2[mt][h] += __shfl_xor_sync(0xffffffffu, s2[mt][h], o);
                    }
            float2* red = reinterpret_cast<float2*>(sm + 76800);
            if ((lane & 3) == 0){
#pragma unroll
                for (int mt = 0; mt < 2; mt++)
#pragma unroll
                    for (int h = 0; h < 2; h++){
                        int r = wm * 32 + mt * 16 + (lane >> 2) + 8 * h;
                        red[r * 4 + wn] = make_float2(s1[mt][h], s2[mt][h]);
                    }
            }
            __syncthreads();
            float2* musd = reinterpret_cast<float2*>(sm + 78848);
            if (tid < 64){
                float S1 = 0.f, S2 = 0.f;
#pragma unroll
                for (int w = 0; w < 4; w++){ float2 v = red[tid * 4 + w]; S1 += v.x; S2 += v.y; }
                float mu = S1 * (1.f / 256.f);
                float rstd = rsqrtf(fmaf(-mu, mu, S2 * (1.f / 256.f)) + 1e-5f);
                musd[tid] = make_float2(mu, rstd);
            }
            __syncthreads();
#pragma unroll
            for (int mt = 0; mt < 2; mt++)
#pragma unroll
                for (int h = 0; h < 2; h++){
                    int r = wm * 32 + mt * 16 + (lane >> 2) + 8 * h;
                    float2 ms = musd[r];
                    u8*  orow  = outp + (size_t)(row0 + r) * MIDB;
                    u16* orowf = MIRROR ? (outf + (size_t)(row0 + r) * HFW) : nullptr;
#pragma unroll
                    for (int nt = 0; nt < 8; nt++){
                        int c = cbase + nt * 8;
                        float v0 = vf[mt][nt][2 * h], v1 = vf[mt][nt][2 * h + 1];
                        float o0 = fmaxf(fmaf((v0 - ms.x) * ms.y, __ldg(gamma + c),     __ldg(beta + c)),     0.f);
                        float o1 = fmaxf(fmaf((v1 - ms.x) * ms.y, __ldg(gamma + c + 1), __ldg(beta + c + 1)), 0.f);
                        *reinterpret_cast<u16*>(orow + c) = pk8(o0, o1);
                        if (MIRROR) *reinterpret_cast<u32*>(orowf + c) = f2h2(o0, o1);
                    }
                }
        } else {
            float* part = reinterpret_cast<float*>(sm + 76800);
#pragma unroll
            for (int mt = 0; mt < 2; mt++)
#pragma unroll
                for (int h = 0; h < 2; h++){
                    int r = wm * 32 + mt * 16 + (lane >> 2) + 8 * h;
                    float s = 0.f;
#pragma unroll
                    for (int nt = 0; nt < 8; nt++){
                        int c  = cbase + nt * 8;
                        int gc = ncol0 + c;
                        float2 p = (h == 0) ? h2f(acc[mt][nt][0]) : h2f(acc[mt][nt][1]);
                        float v0 = p.x + __ldg(bias + gc);
                        float v1 = p.y + __ldg(bias + gc + 1);
                        float t0 = fmaxf(fmaf(v0, g_sc[gc],     g_sh[gc]),     0.f);
                        float t1 = fmaxf(fmaf(v1, g_sc[gc + 1], g_sh[gc + 1]), 0.f);
                        s = fmaf(t0, __ldg(gamma + gc), s);
                        s = fmaf(t1, __ldg(gamma + gc + 1), s);
                    }
                    s += __shfl_xor_sync(0xffffffffu, s, 1);
                    s += __shfl_xor_sync(0xffffffffu, s, 2);
                    if ((lane & 3) == 0) part[r * 4 + wn] = s;
                }
            __syncthreads();
            if (tid < 64){
                float S = part[tid * 4] + part[tid * 4 + 1] + part[tid * 4 + 2] + part[tid * 4 + 3];
                g_part[(size_t)(t & 1) * ROWS + row0 + tid] = S;
            }
        }
    }
}

// ---------------- tail: combine partials, +b2, mask; reset counters ----------------
__global__ void mask_kernel(const float* __restrict__ obs, const float* __restrict__ b2,
                            float* __restrict__ out){
    int idx = blockIdx.x * 256 + threadIdx.x;
    int b = idx >> 10, n = idx & 1023;
    float y = g_part[idx] + g_part[ROWS + idx] + b2[0];
    out[idx] = (obs[(size_t)b * NBSTRIDE + n] != 0.f) ? y : MIN_VAL;
    if (idx < 8) g_ctr[idx] = 0u;
}

// ---------------- launch ----------------
extern "C" void kernel_launch(void* const* d_in, const int* in_sizes, int n_in,
                              void* d_out, int out_size) {
    const float* obs  = (const float*)d_in[0];
    const float* W0   = (const float*)d_in[3];
    const float* b0   = (const float*)d_in[4];
    const float* g0   = (const float*)d_in[5];
    const float* be0  = (const float*)d_in[6];
    const float* Ws   = (const float*)d_in[7];
    const float* bs   = (const float*)d_in[8];
    const float* gs   = (const float*)d_in[9];
    const float* bes  = (const float*)d_in[10];
    const float* W1   = (const float*)d_in[11];
    const float* b1   = (const float*)d_in[12];
    const float* bn_g = (const float*)d_in[13];
    const float* bn_b = (const float*)d_in[14];
    const float* bn_m = (const float*)d_in[15];
    const float* bn_v = (const float*)d_in[16];
    const float* W2   = (const float*)d_in[17];
    const float* b2   = (const float*)d_in[18];
    float* out = (float*)d_out;

    u8 *hc, *w0t, *wst, *w1t; u16* hf;
    cudaGetSymbolAddress((void**)&hc,  g_hc);
    cudaGetSymbolAddress((void**)&hf,  g_hf);
    cudaGetSymbolAddress((void**)&w0t, g_w0t);
    cudaGetSymbolAddress((void**)&wst, g_wst);
    cudaGetSymbolAddress((void**)&w1t, g_w1t);

    cudaFuncSetAttribute(gemm_mma<64,   true,  true,  32,  true >, cudaFuncAttributeMaxDynamicSharedMemorySize, SMTOT);
    cudaFuncSetAttribute(gemm_mma<256,  true,  true,  256, true >, cudaFuncAttributeMaxDynamicSharedMemorySize, SMTOT);
    cudaFuncSetAttribute(gemm_mma<256,  true,  true,  256, false>, cudaFuncAttributeMaxDynamicSharedMemorySize, SMTOT);
    cudaFuncSetAttribute(gemm_mma<1088, false, false, 256, false>, cudaFuncAttributeMaxDynamicSharedMemorySize, SMTOT);

    prep_all<<<2978, 256>>>(W0, Ws, W1, bn_g, bn_b, bn_m, bn_v);
    xcvt<<<1024, 256>>>(obs);

    // Layer 0: agg(x from f16 mirror col 0) -> h1 (e4m3 col 32 + f16 mirror col 32)
    gemm_mma<64, true, true, 32, true><<<GRID_P, 256, SMTOT>>>(
        hc, hf, w0t, 0, 1024, b0, g0, be0, hc + 32, hf + 32);

    // Layers 1..2: agg(h_l from mirror) -> h_{l+1} (e4m3 + mirror)
    for (int l = 1; l < 3; l++) {
        gemm_mma<256, true, true, 256, true><<<GRID_P, 256, SMTOT>>>(
            hc, hf + 32 + (l - 1) * 256, wst + (size_t)(l - 1) * 65536, l, 1024,
            bs + (l - 1) * 256, gs + (l - 1) * 256, bes + (l - 1) * 256,
            hc + 32 + l * 256, hf + 32 + l * 256);
    }
    // Layer 3: agg(h3 from mirror) -> h4 (e4m3 only)
    gemm_mma<256, true, true, 256, false><<<GRID_P, 256, SMTOT>>>(
        hc, hf + 32 + 2 * 256, wst + (size_t)2 * 65536, 3, 1024,
        bs + 2 * 256, gs + 2 * 256, bes + 2 * 256,
        hc + 32 + 3 * 256, nullptr);

    // Head: fused GEMM + BN + ReLU + W2-dot -> g_part
    gemm_mma<1088, false, false, 256, false><<<GRID_P, 256, SMTOT>>>(
        hc, nullptr, w1t, 4, 2048, b1, W2, nullptr, nullptr, nullptr);

    mask_kernel<<<256, 256>>>(obs, b2, out);
}

// round 13
// speedup vs baseline: 1.1791x; 1.1791x over previous
#include <cuda_runtime.h>
#include <cuda_bf16.h>
#include <cuda_fp16.h>

typedef unsigned int u32;
typedef unsigned char u8;
typedef unsigned short u16;

#define ROWS 65536
#define NBSTRIDE 33792
#define MIDB 1088              // padded concat stride (1056 data + 32 zeros)
#define MIN_VAL (-10000000.0f)
#define GRID_P 304

// ---------------- persistent scratch (BSS, zero-init) ----------------
__device__ u8    g_hc [(size_t)ROWS * MIDB];   // fp8: [x(32) | h1..h4 | zeros]
__device__ u8    g_w0t[256 * 64];              // W0^T [N=256][K=64], k>=32 zero
__device__ u8    g_wst[3][256 * 256];          // Ws^T fp8
__device__ u8    g_w1t[(size_t)512 * 1088];    // W1^T fp8, k>=1056 zero
__device__ float g_part[2 * ROWS];             // head partial dots per N-half
__device__ float g_sc[512], g_sh[512];         // folded BN scale/shift
__device__ u32   g_ctr[8];                     // dynamic tile counters

// ---------------- helpers ----------------
__device__ __forceinline__ u32 s2u(const void* p){
    u32 a;
    asm("{ .reg .u64 t; cvta.to.shared.u64 t, %1; cvt.u32.u64 %0, t; }" : "=r"(a) : "l"(p));
    return a;
}
__device__ __forceinline__ void cpa16(u32 dst, const void* src){
    asm volatile("cp.async.cg.shared.global [%0], [%1], 16;" :: "r"(dst), "l"(src));
}
#define CP_COMMIT() asm volatile("cp.async.commit_group;" ::: "memory")
#define CP_WAIT(n)  asm volatile("cp.async.wait_group %0;" :: "n"(n) : "memory")

__device__ __forceinline__ void mma_fp8_h(u32* c, const u32* a, const u32* b){
    asm volatile("mma.sync.aligned.m16n8k32.row.col.f16.e4m3.e4m3.f16 "
        "{%0,%1}, {%2,%3,%4,%5}, {%6,%7}, {%0,%1};"
        : "+r"(c[0]), "+r"(c[1])
        : "r"(a[0]), "r"(a[1]), "r"(a[2]), "r"(a[3]), "r"(b[0]), "r"(b[1]));
}
#define LDSM4(r0, r1, r2, r3, addr) \
    asm volatile("ldmatrix.sync.aligned.m8n8.x4.shared.b16 {%0,%1,%2,%3}, [%4];" \
        : "=r"(r0), "=r"(r1), "=r"(r2), "=r"(r3) : "r"(addr))

__device__ __forceinline__ u16 pk8(float lo, float hi){
    u16 t;
    asm("cvt.rn.satfinite.e4m3x2.f32 %0, %1, %2;" : "=h"(t) : "f"(hi), "f"(lo));
    return t;
}
__device__ __forceinline__ u8 cvt1(float v){ return (u8)(pk8(v, 0.f) & 0xff); }
__device__ __forceinline__ float2 h2f(u32 h){
    return __half22float2(*reinterpret_cast<__half2*>(&h));
}
__device__ __forceinline__ void hacc_fp8x4(u32& a0, u32& a1, u32 v){
    u32 f0, f1;
    asm("cvt.rn.f16x2.e4m3x2 %0, %1;" : "=r"(f0) : "h"((u16)(v & 0xffff)));
    asm("cvt.rn.f16x2.e4m3x2 %0, %1;" : "=r"(f1) : "h"((u16)(v >> 16)));
    asm("add.rn.f16x2 %0, %0, %1;" : "+r"(a0) : "r"(f0));
    asm("add.rn.f16x2 %0, %0, %1;" : "+r"(a1) : "r"(f1));
}
__device__ __forceinline__ u32 pack2h(u32 h0, u32 h1){
    u16 a, b;
    asm("cvt.rn.satfinite.e4m3x2.f16x2 %0, %1;" : "=h"(a) : "r"(h0));
    asm("cvt.rn.satfinite.e4m3x2.f16x2 %0, %1;" : "=h"(b) : "r"(h1));
    return (u32)a | ((u32)b << 16);
}

// ---------------- merged prep kernel ----------------
__global__ void prep_all(const float* __restrict__ W0, const float* __restrict__ Ws,
                         const float* __restrict__ W1,
                         const float* __restrict__ bn_g, const float* __restrict__ bn_b,
                         const float* __restrict__ bn_m, const float* __restrict__ bn_v){
    int blk = blockIdx.x, tid = threadIdx.x;
    if (blk < 32){
        int i = blk * 256 + tid;
        int n = i >> 5, k = i & 31;
        g_w0t[n * 64 + k] = cvt1(W0[k * 256 + n]);
    } else if (blk < 800){
        int i = (blk - 32) * 256 + tid;
        int l = i >> 16, r = i & 65535;
        int n = r >> 8, k = r & 255;
        g_wst[l][n * 256 + k] = cvt1(Ws[l * 65536 + k * 256 + n]);
    } else if (blk < 2976){
        int i = (blk - 800) * 256 + tid;
        int n = i / 1088, k = i - n * 1088;
        g_w1t[i] = (k < 1056) ? cvt1(W1[k * 512 + n]) : (u8)0;
    } else {
        int i = (blk - 2976) * 256 + tid;
        if (i < 512){
            float sc = bn_g[i] * rsqrtf(bn_v[i] + 1e-5f);
            g_sc[i] = sc;
            g_sh[i] = bn_b[i] - bn_m[i] * sc;
        }
    }
}

__global__ void xcvt(const float* __restrict__ obs){
    int q = blockIdx.x * 256 + threadIdx.x;
    int row = q >> 2, j = q & 3;
    int b = row >> 10, n = row & 1023;
    const float4* s = reinterpret_cast<const float4*>(obs + (size_t)b * NBSTRIDE + 1024 + n * 32 + j * 8);
    float4 a = s[0], c = s[1];
    u32 w0 = (u32)pk8(a.x, a.y) | ((u32)pk8(a.z, a.w) << 16);
    u32 w1 = (u32)pk8(c.x, c.y) | ((u32)pk8(c.z, c.w) << 16);
    *reinterpret_cast<uint2*>(g_hc + (size_t)row * MIDB + j * 8) = make_uint2(w0, w1);
}

// ---------------- persistent FP8 layer GEMM (R11: pipelined fused agg + LN) ----------
// Tile 64x256, 256 thr, occ 2, 8 warps (wm=wid&1, wn=wid>>1), warp tile 32x64.
// K chunk = 64 (2 k32 mma). 3-stage. Stage: A 64x80 @0 (5120), B 256x80 @5120 = 25600.
// red @76800, musd @78848. Total 79360.
#define SMTOT 79360
template<int KFULL, bool AGG, int AW>
__global__ void __launch_bounds__(256, 2)
gemm_ln(const u8* __restrict__ A, const u8* __restrict__ Bt, int slot, int ntiles,
        const float* __restrict__ bias, const float* __restrict__ gamma,
        const float* __restrict__ beta, u8* __restrict__ outp)
{
    extern __shared__ char sm[];
    __shared__ u32 s_tile;
    const u32 sb = s2u(sm);
    const int tid  = threadIdx.x;
    const int lane = tid & 31, wid = tid >> 5;
    const int wm = wid & 1, wn = wid >> 1;
    constexpr int NC = KFULL / 64;

    const int ar = tid >> 2, aseg = tid & 3;

    for (;;){
        __syncthreads();
        if (tid == 0) s_tile = atomicAdd(&g_ctr[slot], 1u);
        __syncthreads();
        const u32 t = s_tile;
        if (t >= (u32)ntiles) break;

        const int row0 = (int)t << 6;
        const int arow = row0 + ar;
        const int an = arow & 1023, agr = an >> 5, agc = an & 31;

        auto ldgA = [&](int kc, uint4* r){
            const int colb = kc * 64 + aseg * 16;
            r[0] = r[1] = r[2] = r[3] = make_uint4(0u, 0u, 0u, 0u);
            if (AW == 256 || colb < AW){
                const u8* base = A + (size_t)arow * MIDB + colb;
                if (agc > 0)  r[0] = *reinterpret_cast<const uint4*>(base - MIDB);
                if (agc < 31) r[1] = *reinterpret_cast<const uint4*>(base + MIDB);
                if (agr > 0)  r[2] = *reinterpret_cast<const uint4*>(base - 32 * MIDB);
                if (agr < 31) r[3] = *reinterpret_cast<const uint4*>(base + 32 * MIDB);
            }
        };
        auto stsA = [&](int stg, const uint4* r){
            u32 s[8];
#pragma unroll
            for (int e = 0; e < 8; e++) s[e] = 0u;
#pragma unroll
            for (int j = 0; j < 4; j++){
                hacc_fp8x4(s[0], s[1], r[j].x);
                hacc_fp8x4(s[2], s[3], r[j].y);
                hacc_fp8x4(s[4], s[5], r[j].z);
                hacc_fp8x4(s[6], s[7], r[j].w);
            }
            *reinterpret_cast<uint4*>(sm + (u32)stg * 25600u + (u32)(ar * 80 + aseg * 16)) =
                make_uint4(pack2h(s[0], s[1]), pack2h(s[2], s[3]),
                           pack2h(s[4], s[5]), pack2h(s[6], s[7]));
        };
        auto cpA = [&](int kc, int stg){
            cpa16(sb + (u32)stg * 25600u + (u32)(ar * 80 + aseg * 16),
                  A + (size_t)arow * MIDB + kc * 64 + aseg * 16);
        };
        auto cpB = [&](int kc, int stg){
#pragma unroll
            for (int i = 0; i < 4; i++){
                int q = tid + 256 * i;
                int n = q >> 2, seg = q & 3;
                cpa16(sb + (u32)stg * 25600u + 5120u + (u32)(n * 80 + seg * 16),
                      Bt + (size_t)n * KFULL + kc * 64 + seg * 16);
            }
        };

        u32 acc[2][8][2];
#pragma unroll
        for (int mt = 0; mt < 2; mt++)
#pragma unroll
            for (int nt = 0; nt < 8; nt++){ acc[mt][nt][0] = 0u; acc[mt][nt][1] = 0u; }

        uint4 ra[4];
#pragma unroll
        for (int p = 0; p < 2; p++){
            if (p < NC){
                if (AGG){ ldgA(p, ra); stsA(p, ra); }
                else    cpA(p, p);
                cpB(p, p);
            }
            CP_COMMIT();
        }

        for (int kc = 0; kc < NC; kc++){
            const bool pre = (kc + 2 < NC);
            const int stg2 = (kc + 2) % 3;
            if (pre){
                if (AGG) ldgA(kc + 2, ra);
                else     cpA(kc + 2, stg2);
                cpB(kc + 2, stg2);
            }
            CP_COMMIT();
            CP_WAIT(2);
            __syncthreads();

            const u32 Ab = sb + (u32)(kc % 3) * 25600u;
            const u32 Bb = Ab + 5120u;
#pragma unroll
            for (int s = 0; s < 2; s++){
                u32 a[2][4], b[8][2];
#pragma unroll
                for (int mt = 0; mt < 2; mt++){
                    u32 addr = Ab + (u32)((wm * 32 + mt * 16 + (lane & 7) + ((lane >> 3) & 1) * 8) * 80
                                          + s * 32 + (lane >> 4) * 16);
                    LDSM4(a[mt][0], a[mt][1], a[mt][2], a[mt][3], addr);
                }
#pragma unroll
                for (int np = 0; np < 4; np++){
                    u32 addr = Bb + (u32)((wn * 64 + (np * 2 + (lane >> 4)) * 8 + (lane & 7)) * 80
                                          + s * 32 + ((lane >> 3) & 1) * 16);
                    LDSM4(b[np * 2][0], b[np * 2][1], b[np * 2 + 1][0], b[np * 2 + 1][1], addr);
                }
#pragma unroll
                for (int mt = 0; mt < 2; mt++)
#pragma unroll
                    for (int nt = 0; nt < 8; nt++)
                        mma_fp8_h(acc[mt][nt], a[mt], b[nt]);
            }
            if (AGG && pre) stsA(stg2, ra);
        }
        __syncthreads();

        const int cbase = wn * 64 + (lane & 3) * 2;
        float vf[2][8][4];
        float s1[2][2] = {{0,0},{0,0}}, s2[2][2] = {{0,0},{0,0}};
#pragma unroll
        for (int mt = 0; mt < 2; mt++)
#pragma unroll
            for (int nt = 0; nt < 8; nt++){
                int c = cbase + nt * 8;
                float b0 = __ldg(bias + c), b1v = __ldg(bias + c + 1);
                float2 p0 = h2f(acc[mt][nt][0]);
                float2 p1 = h2f(acc[mt][nt][1]);
                float v0 = p0.x + b0, v1 = p0.y + b1v;
                float v2 = p1.x + b0, v3 = p1.y + b1v;
                vf[mt][nt][0] = v0; vf[mt][nt][1] = v1;
                vf[mt][nt][2] = v2; vf[mt][nt][3] = v3;
                s1[mt][0] += v0 + v1; s2[mt][0] = fmaf(v0, v0, fmaf(v1, v1, s2[mt][0]));
                s1[mt][1] += v2 + v3; s2[mt][1] = fmaf(v2, v2, fmaf(v3, v3, s2[mt][1]));
            }
#pragma unroll
        for (int o = 1; o <= 2; o <<= 1)
#pragma unroll
            for (int mt = 0; mt < 2; mt++)
#pragma unroll
                for (int h = 0; h < 2; h++){
                    s1[mt][h] += __shfl_xor_sync(0xffffffffu, s1[mt][h], o);
                    s2[mt][h] += __shfl_xor_sync(0xffffffffu, s2[mt][h], o);
                }
        float2* red = reinterpret_cast<float2*>(sm + 76800);
        if ((lane & 3) == 0){
#pragma unroll
            for (int mt = 0; mt < 2; mt++)
#pragma unroll
                for (int h = 0; h < 2; h++){
                    int r = wm * 32 + mt * 16 + (lane >> 2) + 8 * h;
                    red[r * 4 + wn] = make_float2(s1[mt][h], s2[mt][h]);
                }
        }
        __syncthreads();
        float2* musd = reinterpret_cast<float2*>(sm + 78848);
        if (tid < 64){
            float S1 = 0.f, S2 = 0.f;
#pragma unroll
            for (int w = 0; w < 4; w++){ float2 v = red[tid * 4 + w]; S1 += v.x; S2 += v.y; }
            float mu = S1 * (1.f / 256.f);
            float rstd = rsqrtf(fmaf(-mu, mu, S2 * (1.f / 256.f)) + 1e-5f);
            musd[tid] = make_float2(mu, rstd);
        }
        __syncthreads();
#pragma unroll
        for (int mt = 0; mt < 2; mt++)
#pragma unroll
            for (int h = 0; h < 2; h++){
                int r = wm * 32 + mt * 16 + (lane >> 2) + 8 * h;
                float2 ms = musd[r];
                u8* orow = outp + (size_t)(row0 + r) * MIDB;
#pragma unroll
                for (int nt = 0; nt < 8; nt++){
                    int c = cbase + nt * 8;
                    float v0 = vf[mt][nt][2 * h], v1 = vf[mt][nt][2 * h + 1];
                    float o0 = fmaxf(fmaf((v0 - ms.x) * ms.y, __ldg(gamma + c),     __ldg(beta + c)),     0.f);
                    float o1 = fmaxf(fmaf((v1 - ms.x) * ms.y, __ldg(gamma + c + 1), __ldg(beta + c + 1)), 0.f);
                    *reinterpret_cast<u16*>(orow + c) = pk8(o0, o1);
                }
            }
    }
}

// ---------------- head: tile 128x256, warp tile 64x64, 3-stage, fused BN/ReLU/W2 ----
// Stage: A 128x80 @0 (10240), B 256x80 @10240 (20480) = 30720; x3 = 92160.
// Epilogue scratch aliased into stage 2 (sm+61440): safe — chunk14 (stage2) is the last
// user and is consumed by iter 14 < NC-1; last prefetches land in stages 0/1.
#define SMTOT_H 92160
__global__ void __launch_bounds__(256, 2)
gemm_head(const u8* __restrict__ A, const u8* __restrict__ Bt,
          const float* __restrict__ b1, const float* __restrict__ W2)
{
    extern __shared__ char sm[];
    __shared__ u32 s_tile;
    const u32 sb = s2u(sm);
    const int tid  = threadIdx.x;
    const int lane = tid & 31, wid = tid >> 5;
    const int wm = wid & 1, wn = wid >> 1;
    constexpr int NC = 17;                        // K = 1088

    for (;;){
        __syncthreads();
        if (tid == 0) s_tile = atomicAdd(&g_ctr[4], 1u);
        __syncthreads();
        const u32 t = s_tile;
        if (t >= 1024u) break;

        const int row0  = (int)(t >> 1) << 7;
        const int ncol0 = (int)(t & 1) << 8;
        const u8* Bp = Bt + (size_t)ncol0 * 1088;

        auto cpA = [&](int kc, int stg){
#pragma unroll
            for (int i = 0; i < 2; i++){          // 128 rows x 4 segs = 512
                int q = tid + 256 * i;
                int r = q >> 2, seg = q & 3;
                cpa16(sb + (u32)stg * 30720u + (u32)(r * 80 + seg * 16),
                      A + (size_t)(row0 + r) * MIDB + kc * 64 + seg * 16);
            }
        };
        auto cpB = [&](int kc, int stg){
#pragma unroll
            for (int i = 0; i < 4; i++){          // 256 rows x 4 segs = 1024
                int q = tid + 256 * i;
                int n = q >> 2, seg = q & 3;
                cpa16(sb + (u32)stg * 30720u + 10240u + (u32)(n * 80 + seg * 16),
                      Bp + (size_t)n * 1088 + kc * 64 + seg * 16);
            }
        };

        u32 acc[4][8][2];
#pragma unroll
        for (int mt = 0; mt < 4; mt++)
#pragma unroll
            for (int nt = 0; nt < 8; nt++){ acc[mt][nt][0] = 0u; acc[mt][nt][1] = 0u; }

#pragma unroll
        for (int p = 0; p < 2; p++){
            cpA(p, p); cpB(p, p);
            CP_COMMIT();
        }

        for (int kc = 0; kc < NC; kc++){
            if (kc + 2 < NC){
                int stg2 = (kc + 2) % 3;
                cpA(kc + 2, stg2); cpB(kc + 2, stg2);
            }
            CP_COMMIT();
            CP_WAIT(2);
            __syncthreads();

            const u32 Ab = sb + (u32)(kc % 3) * 30720u;
            const u32 Bb = Ab + 10240u;
#pragma unroll
            for (int s = 0; s < 2; s++){
                u32 a[4][4], b[8][2];
#pragma unroll
                for (int mt = 0; mt < 4; mt++){
                    u32 addr = Ab + (u32)((wm * 64 + mt * 16 + (lane & 7) + ((lane >> 3) & 1) * 8) * 80
                                          + s * 32 + (lane >> 4) * 16);
                    LDSM4(a[mt][0], a[mt][1], a[mt][2], a[mt][3], addr);
                }
#pragma unroll
                for (int np = 0; np < 4; np++){
                    u32 addr = Bb + (u32)((wn * 64 + (np * 2 + (lane >> 4)) * 8 + (lane & 7)) * 80
                                          + s * 32 + ((lane >> 3) & 1) * 16);
                    LDSM4(b[np * 2][0], b[np * 2][1], b[np * 2 + 1][0], b[np * 2 + 1][1], addr);
                }
#pragma unroll
                for (int mt = 0; mt < 4; mt++)
#pragma unroll
                    for (int nt = 0; nt < 8; nt++)
                        mma_fp8_h(acc[mt][nt], a[mt], b[nt]);
            }
        }
        __syncthreads();

        // epilogue: bias -> BN -> ReLU -> dot(W2 slice) -> per-row partial
        const int cbase = wn * 64 + (lane & 3) * 2;
        float* part = reinterpret_cast<float*>(sm + 61440);   // [128][4], aliases stage 2
#pragma unroll
        for (int mt = 0; mt < 4; mt++)
#pragma unroll
            for (int h = 0; h < 2; h++){
                int r = wm * 64 + mt * 16 + (lane >> 2) + 8 * h;
                float s = 0.f;
#pragma unroll
                for (int nt = 0; nt < 8; nt++){
                    int c  = cbase + nt * 8;
                    int gc = ncol0 + c;
                    float2 p = (h == 0) ? h2f(acc[mt][nt][0]) : h2f(acc[mt][nt][1]);
                    float v0 = p.x + __ldg(b1 + gc);
                    float v1 = p.y + __ldg(b1 + gc + 1);
                    float t0 = fmaxf(fmaf(v0, g_sc[gc],     g_sh[gc]),     0.f);
                    float t1 = fmaxf(fmaf(v1, g_sc[gc + 1], g_sh[gc + 1]), 0.f);
                    s = fmaf(t0, __ldg(W2 + gc), s);
                    s = fmaf(t1, __ldg(W2 + gc + 1), s);
                }
                s += __shfl_xor_sync(0xffffffffu, s, 1);
                s += __shfl_xor_sync(0xffffffffu, s, 2);
                if ((lane & 3) == 0) part[r * 4 + wn] = s;
            }
        __syncthreads();
        if (tid < 128){
            float S = part[tid * 4] + part[tid * 4 + 1] + part[tid * 4 + 2] + part[tid * 4 + 3];
            g_part[(size_t)(t & 1) * ROWS + row0 + tid] = S;
        }
    }
}

// ---------------- tail: combine partials, +b2, mask; reset counters ----------------
__global__ void mask_kernel(const float* __restrict__ obs, const float* __restrict__ b2,
                            float* __restrict__ out){
    int idx = blockIdx.x * 256 + threadIdx.x;
    int b = idx >> 10, n = idx & 1023;
    float y = g_part[idx] + g_part[ROWS + idx] + b2[0];
    out[idx] = (obs[(size_t)b * NBSTRIDE + n] != 0.f) ? y : MIN_VAL;
    if (idx < 8) g_ctr[idx] = 0u;
}

// ---------------- launch ----------------
extern "C" void kernel_launch(void* const* d_in, const int* in_sizes, int n_in,
                              void* d_out, int out_size) {
    const float* obs  = (const float*)d_in[0];
    const float* W0   = (const float*)d_in[3];
    const float* b0   = (const float*)d_in[4];
    const float* g0   = (const float*)d_in[5];
    const float* be0  = (const float*)d_in[6];
    const float* Ws   = (const float*)d_in[7];
    const float* bs   = (const float*)d_in[8];
    const float* gs   = (const float*)d_in[9];
    const float* bes  = (const float*)d_in[10];
    const float* W1   = (const float*)d_in[11];
    const float* b1   = (const float*)d_in[12];
    const float* bn_g = (const float*)d_in[13];
    const float* bn_b = (const float*)d_in[14];
    const float* bn_m = (const float*)d_in[15];
    const float* bn_v = (const float*)d_in[16];
    const float* W2   = (const float*)d_in[17];
    const float* b2   = (const float*)d_in[18];
    float* out = (float*)d_out;

    u8 *hc, *w0t, *wst, *w1t;
    cudaGetSymbolAddress((void**)&hc,  g_hc);
    cudaGetSymbolAddress((void**)&w0t, g_w0t);
    cudaGetSymbolAddress((void**)&wst, g_wst);
    cudaGetSymbolAddress((void**)&w1t, g_w1t);

    cudaFuncSetAttribute(gemm_ln<64,  true, 32 >, cudaFuncAttributeMaxDynamicSharedMemorySize, SMTOT);
    cudaFuncSetAttribute(gemm_ln<256, true, 256>, cudaFuncAttributeMaxDynamicSharedMemorySize, SMTOT);
    cudaFuncSetAttribute(gemm_head,               cudaFuncAttributeMaxDynamicSharedMemorySize, SMTOT_H);

    prep_all<<<2978, 256>>>(W0, Ws, W1, bn_g, bn_b, bn_m, bn_v);
    xcvt<<<1024, 256>>>(obs);

    // Layer 0: h1 = relu(LN(agg(x) @ W0 + b0)), agg fused into A-load
    gemm_ln<64, true, 32><<<GRID_P, 256, SMTOT>>>(
        hc, w0t, 0, 1024, b0, g0, be0, hc + 32);

    // Layers 1..3 (agg fused)
    for (int l = 1; l < 4; l++) {
        gemm_ln<256, true, 256><<<GRID_P, 256, SMTOT>>>(
            hc + 32 + (l - 1) * 256, wst + (size_t)(l - 1) * 65536, l, 1024,
            bs + (l - 1) * 256, gs + (l - 1) * 256, bes + (l - 1) * 256,
            hc + 32 + l * 256);
    }

    // Head: 128x256 tiles, fused GEMM + BN + ReLU + W2-dot -> g_part
    gemm_head<<<GRID_P, 256, SMTOT_H>>>(hc, w1t, b1, W2);

    // Tail: combine + mask + counter reset
    mask_kernel<<<256, 256>>>(obs, b2, out);
}